// round 2
// baseline (speedup 1.0000x reference)
#include <cuda_runtime.h>

#define NTHREADS 256
#define MAX_BLOCKS 8192

__device__ double g_partial[MAX_BLOCKS];
__device__ unsigned int g_ticket;   // zero-init; last block resets -> graph-replay safe

#define C_PER_SAMPLE 7.1624450756f  // prior+lik constants per sample
#define C_ENTROPY    5.6757541328f  // 0.5*4*(1+log 2pi)

// ---------------- packed f32x2 helpers (Blackwell FFMA2 path) ----------------
union F2 { float2 f; unsigned long long u; };

__device__ __forceinline__ F2 mk2(float a, float b) { F2 r; r.f.x = a; r.f.y = b; return r; }
__device__ __forceinline__ F2 fma2(F2 a, F2 b, F2 c) {
    F2 d; asm("fma.rn.f32x2 %0, %1, %2, %3;" : "=l"(d.u) : "l"(a.u), "l"(b.u), "l"(c.u)); return d;
}
__device__ __forceinline__ F2 add2(F2 a, F2 b) {
    F2 d; asm("add.rn.f32x2 %0, %1, %2;" : "=l"(d.u) : "l"(a.u), "l"(b.u)); return d;
}
__device__ __forceinline__ F2 mul2(F2 a, F2 b) {
    F2 d; asm("mul.rn.f32x2 %0, %1, %2;" : "=l"(d.u) : "l"(a.u), "l"(b.u)); return d;
}
__device__ __forceinline__ F2 relu2(F2 a) {
    F2 r; r.f.x = fmaxf(a.f.x, 0.0f); r.f.y = fmaxf(a.f.y, 0.0f); return r;
}

// ---------------- SMEM weight layout: duplicated for packed LDS --------------
struct MlpSmem {
    float4 w1p[20];   // {w1a, w1a, w1b, w1b}
    float2 b1[20];    // {b, b}
    float4 w2t[100];  // [10][10]: row k = W2[:,k] duplicated pairwise
    float2 b2[12];    // padded
    float4 w3t[36];   // [6][6]: row o = W3[:,o] padded to 12, duplicated
    float2 b3[8];     // padded
};

__device__ __forceinline__ void load_mlp(
    MlpSmem* s, const float* W1, const float* B1,
    const float* W2, const float* B2,
    const float* W3, const float* B3, int OUT, int tid)
{
    if (tid < 20) {
        float a = W1[tid], b = W1[20 + tid];
        s->w1p[tid] = make_float4(a, a, b, b);
        float bb = B1[tid];
        s->b1[tid] = make_float2(bb, bb);
    }
    for (int i = tid; i < 200; i += NTHREADS) {   // i = k*20 + j
        int k = i / 20, j = i % 20;
        float w = W2[j * 10 + k];
        ((float2*)s->w2t)[i] = make_float2(w, w);
    }
    if (tid < 12) { float v = (tid < 10) ? B2[tid] : 0.0f; s->b2[tid] = make_float2(v, v); }
    for (int i = tid; i < OUT * 12; i += NTHREADS) {  // i = o*12 + k
        int o = i / 12, k = i % 12;
        float w = (k < 10) ? W3[k * OUT + o] : 0.0f;
        ((float2*)s->w3t)[i] = make_float2(w, w);
    }
    if (tid < 8) { float v = (tid < OUT) ? B3[tid] : 0.0f; s->b3[tid] = make_float2(v, v); }
}

template <int OUT>
__device__ __forceinline__ void mlp_eval2(const MlpSmem* w, F2 y0, F2 y1, F2* out)
{
    F2 h1[20];
#pragma unroll
    for (int j = 0; j < 20; j++) {
        float4 v = w->w1p[j];
        F2 b; b.f = w->b1[j];
        h1[j] = relu2(fma2(mk2(v.x, v.y), y0, fma2(mk2(v.z, v.w), y1, b)));
    }
    F2 h2[12];
#pragma unroll
    for (int k = 0; k < 10; k++) {
        const float4* wr = &w->w2t[k * 10];
        F2 acc; acc.f = w->b2[k];
#pragma unroll
        for (int q = 0; q < 10; q++) {
            float4 v = wr[q];
            acc = fma2(mk2(v.x, v.y), h1[2 * q],     acc);
            acc = fma2(mk2(v.z, v.w), h1[2 * q + 1], acc);
        }
        h2[k] = relu2(acc);
    }
    h2[10] = mk2(0.0f, 0.0f);
    h2[11] = mk2(0.0f, 0.0f);
#pragma unroll
    for (int o = 0; o < OUT; o++) {
        const float4* wr = &w->w3t[o * 6];
        F2 acc; acc.f = w->b3[o];
#pragma unroll
        for (int q = 0; q < 6; q++) {
            float4 v = wr[q];
            acc = fma2(mk2(v.x, v.y), h2[2 * q],     acc);
            acc = fma2(mk2(v.z, v.w), h2[2 * q + 1], acc);
        }
        out[o] = acc;
    }
}

__device__ __forceinline__ float softplus_f(float x)
{
    return fmaxf(x, 0.0f) + log1pf(__expf(-fabsf(x)));
}

__global__ void __launch_bounds__(NTHREADS)
vi_kernel(const float* __restrict__ y, const float* __restrict__ zs, int N,
          float* __restrict__ out,
          const float* mW1, const float* mb1, const float* mW2,
          const float* mb2, const float* mW3, const float* mb3,
          const float* dW1, const float* db1, const float* dW2,
          const float* db2, const float* dW3, const float* db3,
          const float* oW1, const float* ob1, const float* oW2,
          const float* ob2, const float* oW3, const float* ob3)
{
    __shared__ MlpSmem smu, sld, slo;
    __shared__ double sred[NTHREADS];
    __shared__ float wsum[NTHREADS / 32];
    __shared__ int sh_last;

    int tid = threadIdx.x;
    load_mlp(&smu, mW1, mb1, mW2, mb2, mW3, mb3, 4, tid);
    load_mlp(&sld, dW1, db1, dW2, db2, dW3, db3, 4, tid);
    load_mlp(&slo, oW1, ob1, oW2, ob2, oW3, ob3, 6, tid);
    __syncthreads();

    int g = blockIdx.x * NTHREADS + tid;
    int n0 = 2 * g, n1 = n0 + 1;
    float val = 0.0f;

    if (n0 < N) {
        bool two = (n1 < N);
        float4 yv;
        if (two) {
            yv = ((const float4*)y)[g];
        } else {
            float2 ya = ((const float2*)y)[n0];
            yv = make_float4(ya.x, ya.y, ya.x, ya.y);
            n1 = n0;
        }
        F2 y0 = mk2(yv.x, yv.z);
        F2 y1 = mk2(yv.y, yv.w);

        F2 mu[4], ldr[4], off[6];
        mlp_eval2<4>(&smu, y0, y1, mu);
        mlp_eval2<4>(&sld, y0, y1, ldr);
        mlp_eval2<6>(&slo, y0, y1, off);

        F2 d0 = mk2(softplus_f(ldr[0].f.x), softplus_f(ldr[0].f.y));
        F2 d1 = mk2(softplus_f(ldr[1].f.x), softplus_f(ldr[1].f.y));
        F2 d2 = mk2(softplus_f(ldr[2].f.x), softplus_f(ldr[2].f.y));
        F2 d3 = mk2(softplus_f(ldr[3].f.x), softplus_f(ldr[3].f.y));

        const float4* zp0 = (const float4*)zs + (size_t)n0 * 8;
        const float4* zp1 = (const float4*)zs + (size_t)n1 * 8;

        const F2 m100 = mk2(-100.0f, -100.0f);
        const F2 half2 = mk2(0.5f, 0.5f);
        const F2 nhalf2 = mk2(-0.5f, -0.5f);
        F2 yx100 = mul2(y0, mk2(100.0f, 100.0f));
        F2 yy100 = mul2(y1, mk2(100.0f, 100.0f));

        F2 acc = mk2(0.0f, 0.0f);
#pragma unroll
        for (int p = 0; p < 8; p++) {
            float4 z0 = zp0[p];
            float4 z1 = zp1[p];
            F2 zx = mk2(z0.x, z1.x);
            F2 zy = mk2(z0.y, z1.y);
            F2 zz = mk2(z0.z, z1.z);
            F2 zw = mk2(z0.w, z1.w);

            F2 xi0 = fma2(d0, zx, mu[0]);
            F2 xi1 = fma2(d1, zy, fma2(off[0], zx, mu[1]));
            F2 xi2 = fma2(d2, zz, fma2(off[2], zy, fma2(off[1], zx, mu[2])));
            F2 xi3 = fma2(d3, zw, fma2(off[5], zz,
                          fma2(off[4], zy, fma2(off[3], zx, mu[3]))));

            F2 a1 = xi1;
            F2 a2 = add2(a1, xi2);
            F2 a3 = add2(a2, xi3);

            float s1a, c1a, s2a, c2a, s3a, c3a;
            float s1b, c1b, s2b, c2b, s3b, c3b;
            __sincosf(a1.f.x, &s1a, &c1a);
            __sincosf(a2.f.x, &s2a, &c2a);
            __sincosf(a3.f.x, &s3a, &c3a);
            __sincosf(a1.f.y, &s1b, &c1b);
            __sincosf(a2.f.y, &s2b, &c2b);
            __sincosf(a3.f.y, &s3b, &c3b);

            float pxa = fmaf(0.5f, c1a, fmaf(0.5f, c2a, c3a));
            float pya = xi0.f.x + fmaf(0.5f, s1a, fmaf(0.5f, s2a, s3a));
            float pxb = fmaf(0.5f, c1b, fmaf(0.5f, c2b, c3b));
            float pyb = xi0.f.y + fmaf(0.5f, s1b, fmaf(0.5f, s2b, s3b));

            F2 px = mk2(pxa, pxb);
            F2 py = mk2(pya, pyb);
            F2 rx = fma2(m100, px, yx100);
            F2 ry = fma2(m100, py, yy100);

            F2 t0 = mul2(xi0, mk2(4.0f, 4.0f));
            F2 t1 = add2(xi1, xi1);
            F2 t2 = add2(xi2, xi2);
            F2 t3 = add2(xi3, xi3);
            F2 q  = fma2(t0, t0, fma2(t1, t1, fma2(t2, t2, mul2(t3, t3))));
            F2 r2 = fma2(rx, rx, mul2(ry, ry));

            acc = fma2(nhalf2, add2(q, r2), acc);
            (void)half2;
        }

        float entA = __logf(d0.f.x) + __logf(d1.f.x) + __logf(d2.f.x) + __logf(d3.f.x);
        float entB = __logf(d0.f.y) + __logf(d1.f.y) + __logf(d2.f.y) + __logf(d3.f.y);
        float vA = fmaf(acc.f.x, 0.125f, C_PER_SAMPLE) + C_ENTROPY + entA;
        float vB = fmaf(acc.f.y, 0.125f, C_PER_SAMPLE) + C_ENTROPY + entB;
        val = two ? (vA + vB) : vA;
    }

    // ---- block reduction (deterministic) ----
#pragma unroll
    for (int o = 16; o > 0; o >>= 1)
        val += __shfl_down_sync(0xffffffffu, val, o);
    if ((tid & 31) == 0) wsum[tid >> 5] = val;
    __syncthreads();
    if (tid == 0) {
        double s = 0.0;
#pragma unroll
        for (int w = 0; w < NTHREADS / 32; w++) s += (double)wsum[w];
        g_partial[blockIdx.x] = s;
        __threadfence();
        unsigned t = atomicAdd(&g_ticket, 1u);
        sh_last = (t == gridDim.x - 1) ? 1 : 0;
    }
    __syncthreads();

    // ---- fused finalize: last block reduces all partials deterministically ----
    if (sh_last) {
        __threadfence();
        double s = 0.0;
        for (int i = tid; i < (int)gridDim.x; i += NTHREADS)
            s += __ldcg(&g_partial[i]);
        sred[tid] = s;
        __syncthreads();
#pragma unroll
        for (int st = NTHREADS / 2; st > 0; st >>= 1) {
            if (tid < st) sred[tid] += sred[tid + st];
            __syncthreads();
        }
        if (tid == 0) {
            out[0] = (float)(sred[0] / (double)N);
            __threadfence();
            g_ticket = 0;   // reset for next graph replay
        }
    }
}

extern "C" void kernel_launch(void* const* d_in, const int* in_sizes, int n_in,
                              void* d_out, int out_size)
{
    const float* y  = (const float*)d_in[0];
    const float* zs = (const float*)d_in[1];
    int N = in_sizes[0] / 2;
    int npairs = (N + 1) / 2;
    int nblocks = (npairs + NTHREADS - 1) / NTHREADS;
    if (nblocks > MAX_BLOCKS) nblocks = MAX_BLOCKS;

    vi_kernel<<<nblocks, NTHREADS>>>(
        y, zs, N, (float*)d_out,
        (const float*)d_in[2],  (const float*)d_in[3],  (const float*)d_in[4],
        (const float*)d_in[5],  (const float*)d_in[6],  (const float*)d_in[7],
        (const float*)d_in[8],  (const float*)d_in[9],  (const float*)d_in[10],
        (const float*)d_in[11], (const float*)d_in[12], (const float*)d_in[13],
        (const float*)d_in[14], (const float*)d_in[15], (const float*)d_in[16],
        (const float*)d_in[17], (const float*)d_in[18], (const float*)d_in[19]);
}

// round 3
// speedup vs baseline: 1.2397x; 1.2397x over previous
#include <cuda_runtime.h>

#define NTHREADS 256
#define MAX_BLOCKS 8192

#define C_PER_SAMPLE 7.1624450756f  // prior+lik constants per sample
#define C_ENTROPY    5.6757541328f  // 0.5*4*(1+log 2pi)

// Packed, padded weight layout. Indices compile-time in the main kernel ->
// uniform constant loads (LDCU) on the uniform port, zero smem traffic.
struct WPack {
    float4 l1[3][20];    // (W1[0][j], W1[1][j], b1[j], 0)
    float4 w2[3][10][5]; // w2[m][k][q] = W2[4q..4q+3][k]
    float4 w3[3][6][3];  // w3[m][o][q] = W3[4q..4q+3][o] (k>=10 or o>=OUT -> 0)
    float  b2[3][10];
    float  b3[3][6];
};

__constant__ WPack c_w;
__device__   WPack g_stage;
__device__ double g_partial[MAX_BLOCKS];
__device__ unsigned int g_ticket;   // zero-init; last block resets (graph-replay safe)

// ---------------------------------------------------------------------------
__global__ void pack_kernel(
    const float* mW1, const float* mb1, const float* mW2, const float* mb2,
    const float* mW3, const float* mb3,
    const float* dW1, const float* db1, const float* dW2, const float* db2,
    const float* dW3, const float* db3,
    const float* oW1, const float* ob1, const float* oW2, const float* ob2,
    const float* oW3, const float* ob3)
{
    const float* W1[3] = {mW1, dW1, oW1};
    const float* B1[3] = {mb1, db1, ob1};
    const float* W2[3] = {mW2, dW2, oW2};
    const float* B2[3] = {mb2, db2, ob2};
    const float* W3[3] = {mW3, dW3, oW3};
    const float* B3[3] = {mb3, db3, ob3};
    const int OUT[3] = {4, 4, 6};
    int t = threadIdx.x;

    for (int i = t; i < 60; i += blockDim.x) {
        int m = i / 20, j = i % 20;
        g_stage.l1[m][j] = make_float4(W1[m][j], W1[m][20 + j], B1[m][j], 0.0f);
    }
    for (int i = t; i < 150; i += blockDim.x) {
        int m = i / 50, r = i % 50, k = r / 5, q = r % 5;
        g_stage.w2[m][k][q] = make_float4(
            W2[m][(4 * q + 0) * 10 + k], W2[m][(4 * q + 1) * 10 + k],
            W2[m][(4 * q + 2) * 10 + k], W2[m][(4 * q + 3) * 10 + k]);
    }
    for (int i = t; i < 54; i += blockDim.x) {
        int m = i / 18, r = i % 18, o = r / 3, q = r % 3;
        int Om = OUT[m];
        float v[4];
#pragma unroll
        for (int s = 0; s < 4; s++) {
            int k = 4 * q + s;
            v[s] = (k < 10 && o < Om) ? W3[m][k * Om + o] : 0.0f;
        }
        g_stage.w3[m][o][q] = make_float4(v[0], v[1], v[2], v[3]);
    }
    for (int i = t; i < 30; i += blockDim.x) {
        int m = i / 10, k = i % 10;
        g_stage.b2[m][k] = B2[m][k];
    }
    for (int i = t; i < 18; i += blockDim.x) {
        int m = i / 6, o = i % 6;
        g_stage.b3[m][o] = (o < OUT[m]) ? B3[m][o] : 0.0f;
    }
}

// ---------------------------------------------------------------------------
template <int M, int OUT>
__device__ __forceinline__ void mlp_eval(float y0, float y1, float* out)
{
    float h[20];
#pragma unroll
    for (int j = 0; j < 20; j++) {
        float4 v = c_w.l1[M][j];
        h[j] = fmaxf(fmaf(v.x, y0, fmaf(v.y, y1, v.z)), 0.0f);
    }
    float h2[12];
#pragma unroll
    for (int k = 0; k < 10; k++) {
        float acc = c_w.b2[M][k];
#pragma unroll
        for (int q = 0; q < 5; q++) {
            float4 v = c_w.w2[M][k][q];
            acc = fmaf(v.x, h[4 * q + 0], acc);
            acc = fmaf(v.y, h[4 * q + 1], acc);
            acc = fmaf(v.z, h[4 * q + 2], acc);
            acc = fmaf(v.w, h[4 * q + 3], acc);
        }
        h2[k] = fmaxf(acc, 0.0f);
    }
    h2[10] = 0.0f;
    h2[11] = 0.0f;
#pragma unroll
    for (int o = 0; o < OUT; o++) {
        float acc = c_w.b3[M][o];
#pragma unroll
        for (int q = 0; q < 3; q++) {
            float4 v = c_w.w3[M][o][q];
            acc = fmaf(v.x, h2[4 * q + 0], acc);
            acc = fmaf(v.y, h2[4 * q + 1], acc);
            acc = fmaf(v.z, h2[4 * q + 2], acc);
            acc = fmaf(v.w, h2[4 * q + 3], acc);
        }
        out[o] = acc;
    }
}

__device__ __forceinline__ float softplus_f(float x)
{
    return fmaxf(x, 0.0f) + log1pf(__expf(-fabsf(x)));
}

// ---------------------------------------------------------------------------
__global__ void __launch_bounds__(NTHREADS)
vi_kernel(const float* __restrict__ y, const float* __restrict__ zs, int N,
          float* __restrict__ out)
{
    __shared__ double sred[NTHREADS];
    __shared__ float wsum[NTHREADS / 32];
    __shared__ int sh_last;

    int tid = threadIdx.x;
    int n = blockIdx.x * NTHREADS + tid;
    float val = 0.0f;

    if (n < N) {
        // Front-load the only DRAM traffic (one 128B line) so its latency
        // hides under ~1200 instr of MLP compute.
        const float4* zp = (const float4*)zs + (size_t)n * 8;
        float4 zb[8];
#pragma unroll
        for (int p = 0; p < 8; p++) zb[p] = zp[p];

        float2 yv = ((const float2*)y)[n];

        float mu[4], ldr[4], off[6];
        mlp_eval<0, 4>(yv.x, yv.y, mu);
        mlp_eval<1, 4>(yv.x, yv.y, ldr);
        mlp_eval<2, 6>(yv.x, yv.y, off);

        float d0 = softplus_f(ldr[0]);
        float d1 = softplus_f(ldr[1]);
        float d2 = softplus_f(ldr[2]);
        float d3 = softplus_f(ldr[3]);

        float acc = 0.0f;
#pragma unroll
        for (int p = 0; p < 8; p++) {
            float4 z = zb[p];
            float xi0 = fmaf(d0, z.x, mu[0]);
            float xi1 = fmaf(d1, z.y, fmaf(off[0], z.x, mu[1]));
            float xi2 = fmaf(d2, z.z, fmaf(off[2], z.y, fmaf(off[1], z.x, mu[2])));
            float xi3 = fmaf(d3, z.w, fmaf(off[5], z.z,
                          fmaf(off[4], z.y, fmaf(off[3], z.x, mu[3]))));

            float a1 = xi1;
            float a2 = a1 + xi2;
            float a3 = a2 + xi3;
            float s1, c1, s2, c2, s3, c3;
            __sincosf(a1, &s1, &c1);
            __sincosf(a2, &s2, &c2);
            __sincosf(a3, &s3, &c3);

            float px = fmaf(0.5f, c1, fmaf(0.5f, c2, c3));
            float py = xi0 + fmaf(0.5f, s1, fmaf(0.5f, s2, s3));

            float t0 = xi0 * 4.0f;
            float t1 = xi1 + xi1;
            float t2 = xi2 + xi2;
            float t3 = xi3 + xi3;
            float q = fmaf(t0, t0, fmaf(t1, t1, fmaf(t2, t2, t3 * t3)));

            float rx = (yv.x - px) * 100.0f;
            float ry = (yv.y - py) * 100.0f;
            float r2 = fmaf(rx, rx, ry * ry);

            acc = fmaf(-0.5f, q + r2, acc);
        }

        float datafit = fmaf(acc, 0.125f, C_PER_SAMPLE);
        float entropy = C_ENTROPY + __logf(d0) + __logf(d1) +
                        __logf(d2) + __logf(d3);
        val = datafit + entropy;
    }

    // ---- deterministic block reduction ----
#pragma unroll
    for (int o = 16; o > 0; o >>= 1)
        val += __shfl_down_sync(0xffffffffu, val, o);
    if ((tid & 31) == 0) wsum[tid >> 5] = val;
    __syncthreads();
    if (tid == 0) {
        double s = 0.0;
#pragma unroll
        for (int w = 0; w < NTHREADS / 32; w++) s += (double)wsum[w];
        g_partial[blockIdx.x] = s;
        __threadfence();
        unsigned t = atomicAdd(&g_ticket, 1u);
        sh_last = (t == gridDim.x - 1) ? 1 : 0;
    }
    __syncthreads();

    // ---- fused finalize: last block reduces all partials deterministically ----
    if (sh_last) {
        __threadfence();
        double s = 0.0;
        for (int i = tid; i < (int)gridDim.x; i += NTHREADS)
            s += __ldcg(&g_partial[i]);
        sred[tid] = s;
        __syncthreads();
#pragma unroll
        for (int st = NTHREADS / 2; st > 0; st >>= 1) {
            if (tid < st) sred[tid] += sred[tid + st];
            __syncthreads();
        }
        if (tid == 0) {
            out[0] = (float)(sred[0] / (double)N);
            __threadfence();
            g_ticket = 0;   // reset for next graph replay
        }
    }
}

// ---------------------------------------------------------------------------
extern "C" void kernel_launch(void* const* d_in, const int* in_sizes, int n_in,
                              void* d_out, int out_size)
{
    const float* y  = (const float*)d_in[0];
    const float* zs = (const float*)d_in[1];
    int N = in_sizes[0] / 2;
    int nblocks = (N + NTHREADS - 1) / NTHREADS;
    if (nblocks > MAX_BLOCKS) nblocks = MAX_BLOCKS;

    pack_kernel<<<1, 256>>>(
        (const float*)d_in[2],  (const float*)d_in[3],  (const float*)d_in[4],
        (const float*)d_in[5],  (const float*)d_in[6],  (const float*)d_in[7],
        (const float*)d_in[8],  (const float*)d_in[9],  (const float*)d_in[10],
        (const float*)d_in[11], (const float*)d_in[12], (const float*)d_in[13],
        (const float*)d_in[14], (const float*)d_in[15], (const float*)d_in[16],
        (const float*)d_in[17], (const float*)d_in[18], (const float*)d_in[19]);

    void* caddr = nullptr;
    void* saddr = nullptr;
    cudaGetSymbolAddress(&caddr, c_w);
    cudaGetSymbolAddress(&saddr, g_stage);
    cudaMemcpyAsync(caddr, saddr, sizeof(WPack), cudaMemcpyDeviceToDevice, 0);

    vi_kernel<<<nblocks, NTHREADS>>>(y, zs, N, (float*)d_out);
}